// round 14
// baseline (speedup 1.0000x reference)
#include <cuda_runtime.h>
#include <cuda_fp16.h>
#include <cstdint>

#define BB 2
#define TT 2048
#define DD 1024
#define HH 16
#define HD 64
#define MM (BB*TT)   // 4096
#define WSZ ((size_t)DD*DD)

// Scratch (allocation-free) — all fp16
__device__ __half g_X16[(size_t)MM*DD];    // fp16 x, later attn-out
__device__ __half g_W16[(size_t)4*DD*DD];  // 4 weights, fp16 (q,k,v,o stacked)
__device__ __half g_Q16[(size_t)MM*DD];    // [B,H,T,HD] (scaled*log2e, roped)
__device__ __half g_K16[(size_t)MM*DD];    // [B,H,T,HD] (roped) fp16
__device__ __half g_V16[(size_t)MM*DD];    // [B,H,HD,T] (transposed) fp16

// ---------------------------------------------------------------------------
// helpers
// ---------------------------------------------------------------------------
__device__ __forceinline__ void mma_f16(float* c, const uint32_t* a, const uint32_t* b)
{
    asm volatile(
        "mma.sync.aligned.m16n8k16.row.col.f32.f16.f16.f32 "
        "{%0,%1,%2,%3}, {%4,%5,%6,%7}, {%8,%9}, {%0,%1,%2,%3};"
        : "+f"(c[0]), "+f"(c[1]), "+f"(c[2]), "+f"(c[3])
        : "r"(a[0]), "r"(a[1]), "r"(a[2]), "r"(a[3]), "r"(b[0]), "r"(b[1]));
}

__device__ __forceinline__ void ldsm4(uint32_t* r, uint32_t addr)
{
    asm volatile("ldmatrix.sync.aligned.m8n8.x4.shared.b16 {%0,%1,%2,%3}, [%4];"
        : "=r"(r[0]), "=r"(r[1]), "=r"(r[2]), "=r"(r[3]) : "r"(addr));
}

__device__ __forceinline__ uint32_t pkh(float a, float b)
{
    __half2 t = __halves2half2(__float2half_rn(a), __float2half_rn(b));
    return *(uint32_t*)&t;
}

__device__ __forceinline__ float ex2(float x)
{
    float y;
    asm("ex2.approx.f32 %0, %1;" : "=f"(y) : "f"(x));
    return y;
}

__device__ __forceinline__ void cp16(uint32_t s, const void* g)
{
    asm volatile("cp.async.cg.shared.global [%0], [%1], 16;" :: "r"(s), "l"(g));
}
__device__ __forceinline__ void cpcommit()
{
    asm volatile("cp.async.commit_group;");
}
template<int N> __device__ __forceinline__ void cpwait()
{
    asm volatile("cp.async.wait_group %0;" :: "n"(N));
}

// ---------------------------------------------------------------------------
// One fused fp32->fp16 conversion: x (blocks 0..1023) + 4 weights (1024..2047)
// ---------------------------------------------------------------------------
__global__ void conv_all(const float* __restrict__ x,
                         const float* __restrict__ w0, const float* __restrict__ w1,
                         const float* __restrict__ w2, const float* __restrict__ w3,
                         __half* __restrict__ xd, __half* __restrict__ wd)
{
    const float* src;
    __half* dst;
    size_t b4;
    if (blockIdx.x < 1024) {
        src = x; dst = xd;
        b4 = (size_t)blockIdx.x * 1024 + threadIdx.x;
    } else {
        int wb = blockIdx.x - 1024;
        int wsel = wb >> 8;
        src = (wsel == 0) ? w0 : (wsel == 1) ? w1 : (wsel == 2) ? w2 : w3;
        dst = wd + (size_t)wsel * WSZ;
        b4 = (size_t)(wb & 255) * 1024 + threadIdx.x;
    }
    float4 v[4];
#pragma unroll
    for (int k = 0; k < 4; k++)
        v[k] = *(const float4*)(src + (b4 + k * 256) * 4);
#pragma unroll
    for (int k = 0; k < 4; k++)
        *(uint2*)(dst + (b4 + k * 256) * 4) =
            make_uint2(pkh(v[k].x, v[k].y), pkh(v[k].z, v[k].w));
}

// ---------------------------------------------------------------------------
// fp16 1-product GEMM: C[M,N] = A[M,K] @ W[N,K]^T.
// Block 128x256, BK=64 (16 iters), 3-stage cp.async ring with distance-1
// issue (wait<1> -> barrier -> compute; overwrite target (j+1)%3 is neither
// the laggards' stage (j-1)%3 nor the current j%3), 256 thr, warp tile 64x64.
// ---------------------------------------------------------------------------
#define SAst 72                         // 64 data + 8 pad halfs (144 B rows)
#define A_BYTES (128 * SAst * 2)        // 18432
#define W_BYTES (256 * SAst * 2)        // 36864
#define STAGE_BYTES (A_BYTES + W_BYTES) // 55296
#define CW 264
#define GEMM_SMEM (3 * STAGE_BYTES)     // 165888 (>= 128*CW*4 = 135168)
#define NIT (DD / 64)                   // 16

__global__ __launch_bounds__(256, 1) void gemm_h(
    const __half* __restrict__ Ahg, const __half* __restrict__ Whg,
    __half* __restrict__ dq, __half* __restrict__ dk, __half* __restrict__ dv,
    float* __restrict__ dstf,
    const float* __restrict__ cosT, const float* __restrict__ sinT, int fused)
{
    extern __shared__ unsigned char smraw[];
    const uint32_t sbase = (uint32_t)__cvta_generic_to_shared(smraw);

    const int tid = threadIdx.x;
    const int lane = tid & 31, warp = tid >> 5;
    const int wm = warp & 1, wn = warp >> 1;
    const int g = lane >> 2, tg = lane & 3;
    const int m0 = blockIdx.y * 128, n0 = blockIdx.x * 256;

    float acc[4][8][4];
#pragma unroll
    for (int i = 0; i < 4; i++)
#pragma unroll
        for (int j = 0; j < 8; j++)
#pragma unroll
            for (int r = 0; r < 4; r++) acc[i][j][r] = 0.f;

    const int cr = tid >> 1, cc = tid & 1;   // row 0..127, 32-half chunk 0/1

    auto issue = [&](int k0, int st) {
        uint32_t sb = sbase + st * STAGE_BYTES;
        const __half* a0 = Ahg + (size_t)(m0 + cr) * DD + k0 + cc * 32;
        uint32_t sa = sb + (cr * SAst + cc * 32) * 2;
        cp16(sa, a0); cp16(sa + 16, a0 + 8);
        cp16(sa + 32, a0 + 16); cp16(sa + 48, a0 + 24);
#pragma unroll
        for (int p = 0; p < 2; p++) {
            int rr = cr + p * 128;
            const __half* w0 = Whg + (size_t)(n0 + rr) * DD + k0 + cc * 32;
            uint32_t sw = sb + A_BYTES + (rr * SAst + cc * 32) * 2;
            cp16(sw, w0); cp16(sw + 16, w0 + 8);
            cp16(sw + 32, w0 + 16); cp16(sw + 48, w0 + 24);
        }
    };

    const int lrow = lane & 15, lsel = lane >> 4;
    const int nrow = (lane & 7) + (lane >> 4) * 8;
    const int ksel = (lane >> 3) & 1;

    issue(0, 0); cpcommit();

    for (int j = 0; j < NIT; j++) {
        const int st = j % 3;
        if (j + 1 < NIT) { issue((j + 1) * 64, (j + 1) % 3); cpcommit(); cpwait<1>(); }
        else             { cpwait<0>(); }
        __syncthreads();   // visibility of all threads' copies + ring reuse

        const uint32_t stb = sbase + st * STAGE_BYTES;
#pragma unroll
        for (int s = 0; s < 4; s++) {
            uint32_t fah[4][4];
#pragma unroll
            for (int i = 0; i < 4; i++) {
                uint32_t off = ((wm * 64 + i * 16 + lrow) * SAst + s * 16 + lsel * 8) * 2;
                ldsm4(fah[i], stb + off);
            }
            uint32_t fbh[8][2];
#pragma unroll
            for (int jp = 0; jp < 4; jp++) {
                uint32_t off = ((wn * 64 + jp * 16 + nrow) * SAst + s * 16 + ksel * 8) * 2;
                uint32_t th[4];
                ldsm4(th, stb + A_BYTES + off);
                fbh[2*jp][0] = th[0]; fbh[2*jp][1] = th[1];
                fbh[2*jp+1][0] = th[2]; fbh[2*jp+1][1] = th[3];
            }
#pragma unroll
            for (int i = 0; i < 4; i++)
#pragma unroll
                for (int jn = 0; jn < 8; jn++)
                    mma_f16(acc[i][jn], fah[i], fbh[jn]);
        }
    }
    __syncthreads();   // all stage reads done before Cs aliases smem

    float* Cs = (float*)smraw;
#pragma unroll
    for (int i = 0; i < 4; i++)
#pragma unroll
        for (int jn = 0; jn < 8; jn++) {
            int r = wm * 64 + i * 16 + g, c = wn * 64 + jn * 8 + 2 * tg;
            Cs[r * CW + c]           = acc[i][jn][0];
            Cs[r * CW + c + 1]       = acc[i][jn][1];
            Cs[(r + 8) * CW + c]     = acc[i][jn][2];
            Cs[(r + 8) * CW + c + 1] = acc[i][jn][3];
        }
    __syncthreads();

    const int tx = tid & 63, ty = tid >> 6;
    const int cbase = tx * 4;
    const int bb = m0 >> 11;

    if (!fused) {
#pragma unroll
        for (int i = 0; i < 32; i++) {
            int r = ty * 32 + i, m = m0 + r;
            float4 o = *(const float4*)&Cs[r * CW + cbase];
            *(float4*)(dstf + (size_t)m * DD + n0 + cbase) = o;
        }
        return;
    }

    const int sel = n0 >> 10;
    const int nl = (n0 & 1023) + cbase;
    const int h = nl >> 6, ch = nl & 63;

    if (sel == 2) {
        const int t0 = (m0 & (TT - 1)) + ty * 32;
#pragma unroll
        for (int jj = 0; jj < 4; jj++) {
            int c = cbase + jj, d = (nl + jj) & 63;
            float v[32];
#pragma unroll
            for (int i = 0; i < 32; i++) v[i] = Cs[(ty * 32 + i) * CW + c];
            uint32_t hh[16];
#pragma unroll
            for (int p = 0; p < 16; p++) hh[p] = pkh(v[2*p], v[2*p+1]);
            size_t e = (((size_t)bb * HH + h) * HD + d) * TT + t0;
#pragma unroll
            for (int u = 0; u < 4; u++)
                *(uint4*)&g_V16[e + u * 8] =
                    make_uint4(hh[4*u], hh[4*u+1], hh[4*u+2], hh[4*u+3]);
        }
        return;
    }

    __half* dqk = (sel == 0) ? dq : dk;
    const float qscale = (sel == 0) ? 0.125f * 1.44269504f : 1.0f;
#pragma unroll
    for (int i = 0; i < 32; i++) {
        int r = ty * 32 + i, m = m0 + r;
        int t = m & (TT - 1);
        float vals[4];
#pragma unroll
        for (int jj = 0; jj < 4; jj++) {
            int c = cbase + jj, chj = ch + jj;
            float v = Cs[r * CW + c];
            float prt = (chj < 32) ? -Cs[r * CW + c + 32] : Cs[r * CW + c - 32];
            vals[jj] = (v * cosT[t * HD + chj] + prt * sinT[t * HD + chj]) * qscale;
        }
        size_t e = (((size_t)bb * HH + h) * TT + t) * HD + ch;
        *(uint2*)&dqk[e] = make_uint2(pkh(vals[0], vals[1]), pkh(vals[2], vals[3]));
    }
}

// ---------------------------------------------------------------------------
// fp16 tensor-core flash attention (causal, fixed-max softmax, 1-product).
// 4-stage K/V cp.async ring, one barrier per j-iter, ex2 softmax.
// Paired tiles: CTA bx does qt=15-bx then qt=bx.  (unchanged from R13)
// ---------------------------------------------------------------------------
#define SAT 72
#define TSZ (64 * SAT)
#define ATTN_SMEM (4 * 2 * TSZ * 2)   // 73728

__global__ __launch_bounds__(256) void attn_mma()
{
    extern __shared__ __half smh[];

    const int tid = threadIdx.x;
    const int lane = tid & 31, warp = tid >> 5;
    const int g = lane >> 2, tg = lane & 3;
    const int bx = blockIdx.x;        // 0..7
    const int bh = blockIdx.y;

    const __half* Qb = g_Q16 + (size_t)bh * TT * HD;
    const __half* Kg = g_K16 + (size_t)bh * TT * HD;
    const __half* Vg = g_V16 + (size_t)bh * HD * TT;

    const int cr = tid >> 2, cc = (tid & 3) * 16;
    const int nrow = (lane & 7) + (lane >> 4) * 8;
    const int ksel = (lane >> 3) & 1;

    auto issue = [&](int j, int st) {
        uint32_t sb = (uint32_t)__cvta_generic_to_shared(
            smh + st * 2 * TSZ + cr * SAT + cc);
        const __half* kp = Kg + (size_t)(j * 64 + cr) * HD + cc;
        const __half* vp = Vg + (size_t)cr * TT + j * 64 + cc;
        cp16(sb,           kp); cp16(sb + 16,           kp + 8);
        cp16(sb + TSZ * 2, vp); cp16(sb + TSZ * 2 + 16, vp + 8);
    };

    const uint32_t smb = (uint32_t)__cvta_generic_to_shared(smh);

#pragma unroll 1
    for (int half = 0; half < 2; half++) {
        const int qt = half ? bx : (15 - bx);

        const __half* Qg = Qb + (size_t)qt * 128 * HD;
        uint32_t qf[4][4];
        {
            const int r0 = warp * 16 + g;
#pragma unroll
            for (int s = 0; s < 4; s++) {
                int base = r0 * HD + s * 16 + 2 * tg;
                qf[s][0] = *(const uint32_t*)&Qg[base];
                qf[s][1] = *(const uint32_t*)&Qg[base + 8 * HD];
                qf[s][2] = *(const uint32_t*)&Qg[base + 8];
                qf[s][3] = *(const uint32_t*)&Qg[base + 8 * HD + 8];
            }
        }

        float accO[8][4];
#pragma unroll
        for (int jo = 0; jo < 8; jo++)
#pragma unroll
            for (int r = 0; r < 4; r++) accO[jo][r] = 0.f;
        float l0 = 0.f, l1 = 0.f;

        const int jmax = 2 * qt + 1;
        const int rowg = qt * 128 + warp * 16 + g;
        const int rmax = qt * 128 + warp * 16 + 15;

        issue(0, 0); cpcommit();
        issue(1, 1); cpcommit();

        for (int j = 0; j <= jmax; j++) {
            const int st = j & 3;
            if (j + 2 <= jmax) { issue(j + 2, (j + 2) & 3); cpcommit(); }
            if (j + 2 <= jmax)      cpwait<2>();
            else if (j + 1 <= jmax) cpwait<1>();
            else                    cpwait<0>();
            __syncthreads();

            if (j * 64 <= rmax) {
                const uint32_t skb = smb + (st * 2 * TSZ) * 2;
                const uint32_t svb = skb + TSZ * 2;

                float S[8][4];
#pragma unroll
                for (int jn = 0; jn < 8; jn++)
#pragma unroll
                    for (int r = 0; r < 4; r++) S[jn][r] = 0.f;

#pragma unroll
                for (int s = 0; s < 4; s++) {
#pragma unroll
                    for (int jp = 0; jp < 4; jp++) {
                        uint32_t th[4];
                        ldsm4(th, skb + ((jp * 16 + nrow) * SAT + s * 16 + ksel * 8) * 2);
                        mma_f16(S[2*jp],     qf[s], th);
                        mma_f16(S[2*jp + 1], qf[s], th + 2);
                    }
                }

                const bool diag = (j >= 2 * qt);
#pragma unroll
                for (int jn = 0; jn < 8; jn++) {
                    int kb = j * 64 + jn * 8 + 2 * tg;
                    float p0, p1, p2, p3;
                    if (diag) {
                        p0 = (kb     <= rowg    ) ? ex2(S[jn][0]) : 0.f;
                        p1 = (kb + 1 <= rowg    ) ? ex2(S[jn][1]) : 0.f;
                        p2 = (kb     <= rowg + 8) ? ex2(S[jn][2]) : 0.f;
                        p3 = (kb + 1 <= rowg + 8) ? ex2(S[jn][3]) : 0.f;
                    } else {
                        p0 = ex2(S[jn][0]); p1 = ex2(S[jn][1]);
                        p2 = ex2(S[jn][2]); p3 = ex2(S[jn][3]);
                    }
                    S[jn][0] = p0; S[jn][1] = p1; S[jn][2] = p2; S[jn][3] = p3;
                    l0 += p0 + p1; l1 += p2 + p3;
                }

                uint32_t pf[4][4];
#pragma unroll
                for (int t = 0; t < 4; t++) {
                    pf[t][0] = pkh(S[2*t][0],   S[2*t][1]);
                    pf[t][1] = pkh(S[2*t][2],   S[2*t][3]);
                    pf[t][2] = pkh(S[2*t+1][0], S[2*t+1][1]);
                    pf[t][3] = pkh(S[2*t+1][2], S[2*t+1][3]);
                }

#pragma unroll
                for (int t = 0; t < 4; t++) {
#pragma unroll
                    for (int jp = 0; jp < 4; jp++) {
                        uint32_t th[4];
                        ldsm4(th, svb + ((jp * 16 + nrow) * SAT + t * 16 + ksel * 8) * 2);
                        mma_f16(accO[2*jp],     pf[t], th);
                        mma_f16(accO[2*jp + 1], pf[t], th + 2);
                    }
                }
            }
        }

        l0 += __shfl_xor_sync(0xffffffffu, l0, 1);
        l0 += __shfl_xor_sync(0xffffffffu, l0, 2);
        l1 += __shfl_xor_sync(0xffffffffu, l1, 1);
        l1 += __shfl_xor_sync(0xffffffffu, l1, 2);
        const float inv0 = 1.0f / l0, inv1 = 1.0f / l1;

        const int b = bh / HH, h = bh % HH;
        const int t0 = qt * 128 + warp * 16 + g;
#pragma unroll
        for (int jo = 0; jo < 8; jo++) {
            int d = h * HD + jo * 8 + 2 * tg;
            const size_t e0 = ((size_t)b * TT + t0) * DD + d;
            const size_t e1 = ((size_t)b * TT + t0 + 8) * DD + d;
            *(uint32_t*)&g_X16[e0] = pkh(accO[jo][0] * inv0, accO[jo][1] * inv0);
            *(uint32_t*)&g_X16[e1] = pkh(accO[jo][2] * inv1, accO[jo][3] * inv1);
        }
        __syncthreads();   // smem ring quiesced before next half re-issues
    }
}

// ---------------------------------------------------------------------------
extern "C" void kernel_launch(void* const* d_in, const int* in_sizes, int n_in,
                              void* d_out, int out_size)
{
    const float* x    = (const float*)d_in[0];
    const float* wq   = (const float*)d_in[1];
    const float* wk   = (const float*)d_in[2];
    const float* wv   = (const float*)d_in[3];
    const float* wo   = (const float*)d_in[4];
    const float* cosT = (const float*)d_in[5];
    const float* sinT = (const float*)d_in[6];
    float* out = (float*)d_out;

    __half *x16, *w16, *q16, *k16, *v16;
    cudaGetSymbolAddress((void**)&x16, g_X16);
    cudaGetSymbolAddress((void**)&w16, g_W16);
    cudaGetSymbolAddress((void**)&q16, g_Q16);
    cudaGetSymbolAddress((void**)&k16, g_K16);
    cudaGetSymbolAddress((void**)&v16, g_V16);

    cudaFuncSetAttribute(gemm_h,
                         cudaFuncAttributeMaxDynamicSharedMemorySize, GEMM_SMEM);
    cudaFuncSetAttribute(attn_mma,
                         cudaFuncAttributeMaxDynamicSharedMemorySize, ATTN_SMEM);

    conv_all<<<2048, 256>>>(x, wq, wk, wv, wo, x16, w16);

    // Fused QKV: N = 3072, grid (12, 32)
    gemm_h<<<dim3(12, MM / 128), 256, GEMM_SMEM>>>(
        x16, w16, q16, k16, v16, nullptr, cosT, sinT, 1);
    // Paired causal tiles: grid (8, 32)
    attn_mma<<<dim3(8, BB * HH), 256, ATTN_SMEM>>>();
    // Output projection: N = 1024, grid (4, 32)
    gemm_h<<<dim3(4, MM / 128), 256, GEMM_SMEM>>>(
        x16, w16 + 3 * WSZ, nullptr, nullptr, nullptr, out, cosT, sinT, 0);
}

// round 15
// speedup vs baseline: 1.0596x; 1.0596x over previous
#include <cuda_runtime.h>
#include <cuda_fp16.h>
#include <cstdint>

#define BB 2
#define TT 2048
#define DD 1024
#define HH 16
#define HD 64
#define MM (BB*TT)   // 4096
#define WSZ ((size_t)DD*DD)

// Scratch (allocation-free) — all fp16
__device__ __half g_X16[(size_t)MM*DD];    // fp16 x, later attn-out
__device__ __half g_W16[(size_t)4*DD*DD];  // 4 weights, fp16 (q,k,v,o stacked)
__device__ __half g_Q16[(size_t)MM*DD];    // [B,H,T,HD] (scaled*log2e, roped)
__device__ __half g_K16[(size_t)MM*DD];    // [B,H,T,HD] (roped) fp16
__device__ __half g_V16[(size_t)MM*DD];    // [B,H,HD,T] (transposed) fp16

// ---------------------------------------------------------------------------
// helpers
// ---------------------------------------------------------------------------
__device__ __forceinline__ void mma_f16(float* c, const uint32_t* a, const uint32_t* b)
{
    asm volatile(
        "mma.sync.aligned.m16n8k16.row.col.f32.f16.f16.f32 "
        "{%0,%1,%2,%3}, {%4,%5,%6,%7}, {%8,%9}, {%0,%1,%2,%3};"
        : "+f"(c[0]), "+f"(c[1]), "+f"(c[2]), "+f"(c[3])
        : "r"(a[0]), "r"(a[1]), "r"(a[2]), "r"(a[3]), "r"(b[0]), "r"(b[1]));
}

__device__ __forceinline__ void ldsm4(uint32_t* r, uint32_t addr)
{
    asm volatile("ldmatrix.sync.aligned.m8n8.x4.shared.b16 {%0,%1,%2,%3}, [%4];"
        : "=r"(r[0]), "=r"(r[1]), "=r"(r[2]), "=r"(r[3]) : "r"(addr));
}

__device__ __forceinline__ uint32_t pkh(float a, float b)
{
    __half2 t = __halves2half2(__float2half_rn(a), __float2half_rn(b));
    return *(uint32_t*)&t;
}

__device__ __forceinline__ float ex2(float x)
{
    float y;
    asm("ex2.approx.f32 %0, %1;" : "=f"(y) : "f"(x));
    return y;
}

__device__ __forceinline__ void cp16(uint32_t s, const void* g)
{
    asm volatile("cp.async.cg.shared.global [%0], [%1], 16;" :: "r"(s), "l"(g));
}
__device__ __forceinline__ void cpcommit()
{
    asm volatile("cp.async.commit_group;");
}
template<int N> __device__ __forceinline__ void cpwait()
{
    asm volatile("cp.async.wait_group %0;" :: "n"(N));
}

// ---------------------------------------------------------------------------
// One fused fp32->fp16 conversion: x (blocks 0..1023) + 4 weights (1024..2047)
// ---------------------------------------------------------------------------
__global__ void conv_all(const float* __restrict__ x,
                         const float* __restrict__ w0, const float* __restrict__ w1,
                         const float* __restrict__ w2, const float* __restrict__ w3,
                         __half* __restrict__ xd, __half* __restrict__ wd)
{
    const float* src;
    __half* dst;
    size_t b4;
    if (blockIdx.x < 1024) {
        src = x; dst = xd;
        b4 = (size_t)blockIdx.x * 1024 + threadIdx.x;
    } else {
        int wb = blockIdx.x - 1024;
        int wsel = wb >> 8;
        src = (wsel == 0) ? w0 : (wsel == 1) ? w1 : (wsel == 2) ? w2 : w3;
        dst = wd + (size_t)wsel * WSZ;
        b4 = (size_t)(wb & 255) * 1024 + threadIdx.x;
    }
    float4 v[4];
#pragma unroll
    for (int k = 0; k < 4; k++)
        v[k] = *(const float4*)(src + (b4 + k * 256) * 4);
#pragma unroll
    for (int k = 0; k < 4; k++)
        *(uint2*)(dst + (b4 + k * 256) * 4) =
            make_uint2(pkh(v[k].x, v[k].y), pkh(v[k].z, v[k].w));
}

// ---------------------------------------------------------------------------
// fp16 1-product GEMM: C[M,N] = A[M,K] @ W[N,K]^T.
// Block 128x256, BK=32, 4-stage cp.async ring (distance-2 issue, wait<2>,
// one barrier/iter — R13's proven pipeline), now 512 thr / 16 warps,
// warp tile 32x64 (4m x 4n warps) for 2x latency-hiding warp depth.
// ---------------------------------------------------------------------------
#define SAst 40
#define A_BYTES (128 * SAst * 2)        // 10240
#define W_BYTES (256 * SAst * 2)        // 20480
#define STAGE_BYTES (A_BYTES + W_BYTES) // 30720
#define CW 264
#define GEMM_SMEM (128 * CW * 4)        // 135168 >= 4*STAGE_BYTES (122880)
#define NIT (DD / 32)                   // 32

__global__ __launch_bounds__(512, 1) void gemm_h(
    const __half* __restrict__ Ahg, const __half* __restrict__ Whg,
    __half* __restrict__ dq, __half* __restrict__ dk, __half* __restrict__ dv,
    float* __restrict__ dstf,
    const float* __restrict__ cosT, const float* __restrict__ sinT, int fused)
{
    extern __shared__ unsigned char smraw[];
    const uint32_t sbase = (uint32_t)__cvta_generic_to_shared(smraw);

    const int tid = threadIdx.x;
    const int lane = tid & 31, warp = tid >> 5;     // 16 warps
    const int wm = warp & 3, wn = warp >> 2;        // 4m x 4n
    const int g = lane >> 2, tg = lane & 3;
    const int m0 = blockIdx.y * 128, n0 = blockIdx.x * 256;

    float acc[2][8][4];
#pragma unroll
    for (int i = 0; i < 2; i++)
#pragma unroll
        for (int j = 0; j < 8; j++)
#pragma unroll
            for (int r = 0; r < 4; r++) acc[i][j][r] = 0.f;

    auto issue = [&](int k0, int st) {
        uint32_t sb = sbase + st * STAGE_BYTES;
        {   // A: 128 rows x 32 halfs; thread: row=tid>>2, 8-half chunk=tid&3
            int rr = tid >> 2, ch = tid & 3;
            const __half* a0 = Ahg + (size_t)(m0 + rr) * DD + k0 + ch * 8;
            cp16(sb + (rr * SAst + ch * 8) * 2, a0);
        }
        {   // W: 256 rows x 32 halfs; thread: row=tid>>1, 16-half chunk=tid&1
            int rr = tid >> 1, ch = tid & 1;
            const __half* w0 = Whg + (size_t)(n0 + rr) * DD + k0 + ch * 16;
            uint32_t sw = sb + A_BYTES + (rr * SAst + ch * 16) * 2;
            cp16(sw, w0); cp16(sw + 16, w0 + 8);
        }
    };

    const int lrow = lane & 15, lsel = lane >> 4;
    const int nrow = (lane & 7) + (lane >> 4) * 8;
    const int ksel = (lane >> 3) & 1;

    issue(0, 0); cpcommit();
    issue(32, 1); cpcommit();

    for (int j = 0; j < NIT; j++) {
        const int st = j & 3;
        if (j + 2 < NIT) { issue((j + 2) * 32, (j + 2) & 3); cpcommit(); }
        if (j + 2 < NIT)      cpwait<2>();
        else if (j + 1 < NIT) cpwait<1>();
        else                  cpwait<0>();
        __syncthreads();   // data-ready + ring-reuse (j+2 = j-2 mod 4)

        const uint32_t stb = sbase + st * STAGE_BYTES;
#pragma unroll
        for (int s = 0; s < 2; s++) {
            uint32_t fah[2][4];
#pragma unroll
            for (int i = 0; i < 2; i++) {
                uint32_t off = ((wm * 32 + i * 16 + lrow) * SAst + s * 16 + lsel * 8) * 2;
                ldsm4(fah[i], stb + off);
            }
            uint32_t fbh[8][2];
#pragma unroll
            for (int jp = 0; jp < 4; jp++) {
                uint32_t off = ((wn * 64 + jp * 16 + nrow) * SAst + s * 16 + ksel * 8) * 2;
                uint32_t th[4];
                ldsm4(th, stb + A_BYTES + off);
                fbh[2*jp][0] = th[0]; fbh[2*jp][1] = th[1];
                fbh[2*jp+1][0] = th[2]; fbh[2*jp+1][1] = th[3];
            }
#pragma unroll
            for (int i = 0; i < 2; i++)
#pragma unroll
                for (int jn = 0; jn < 8; jn++)
                    mma_f16(acc[i][jn], fah[i], fbh[jn]);
        }
    }
    __syncthreads();   // all stage reads done before Cs aliases smem

    float* Cs = (float*)smraw;
#pragma unroll
    for (int i = 0; i < 2; i++)
#pragma unroll
        for (int jn = 0; jn < 8; jn++) {
            int r = wm * 32 + i * 16 + g, c = wn * 64 + jn * 8 + 2 * tg;
            Cs[r * CW + c]           = acc[i][jn][0];
            Cs[r * CW + c + 1]       = acc[i][jn][1];
            Cs[(r + 8) * CW + c]     = acc[i][jn][2];
            Cs[(r + 8) * CW + c + 1] = acc[i][jn][3];
        }
    __syncthreads();

    const int tx = tid & 63, ty = tid >> 6;   // 64 col-groups x 8 row-groups
    const int cbase = tx * 4;
    const int bb = m0 >> 11;

    if (!fused) {
#pragma unroll
        for (int i = 0; i < 16; i++) {
            int r = ty * 16 + i, m = m0 + r;
            float4 o = *(const float4*)&Cs[r * CW + cbase];
            *(float4*)(dstf + (size_t)m * DD + n0 + cbase) = o;
        }
        return;
    }

    const int sel = n0 >> 10;
    const int nl = (n0 & 1023) + cbase;
    const int h = nl >> 6, ch = nl & 63;

    if (sel == 2) {
        // V: round fp16 + transpose -> [B,H,HD,T]; 16 t-rows per thread per col
        const int t0 = (m0 & (TT - 1)) + ty * 16;
#pragma unroll
        for (int jj = 0; jj < 4; jj++) {
            int c = cbase + jj, d = (nl + jj) & 63;
            float v[16];
#pragma unroll
            for (int i = 0; i < 16; i++) v[i] = Cs[(ty * 16 + i) * CW + c];
            uint32_t hh[8];
#pragma unroll
            for (int p = 0; p < 8; p++) hh[p] = pkh(v[2*p], v[2*p+1]);
            size_t e = (((size_t)bb * HH + h) * HD + d) * TT + t0;
            *(uint4*)&g_V16[e]     = make_uint4(hh[0], hh[1], hh[2], hh[3]);
            *(uint4*)&g_V16[e + 8] = make_uint4(hh[4], hh[5], hh[6], hh[7]);
        }
        return;
    }

    __half* dqk = (sel == 0) ? dq : dk;
    const float qscale = (sel == 0) ? 0.125f * 1.44269504f : 1.0f;
#pragma unroll
    for (int i = 0; i < 16; i++) {
        int r = ty * 16 + i, m = m0 + r;
        int t = m & (TT - 1);
        float vals[4];
#pragma unroll
        for (int jj = 0; jj < 4; jj++) {
            int c = cbase + jj, chj = ch + jj;
            float v = Cs[r * CW + c];
            float prt = (chj < 32) ? -Cs[r * CW + c + 32] : Cs[r * CW + c - 32];
            vals[jj] = (v * cosT[t * HD + chj] + prt * sinT[t * HD + chj]) * qscale;
        }
        size_t e = (((size_t)bb * HH + h) * TT + t) * HD + ch;
        *(uint2*)&dqk[e] = make_uint2(pkh(vals[0], vals[1]), pkh(vals[2], vals[3]));
    }
}

// ---------------------------------------------------------------------------
// fp16 tensor-core flash attention (causal, fixed-max softmax, 1-product).
// 4-stage K/V cp.async ring, one barrier per j-iter, ex2 softmax.
// Paired tiles: CTA bx does qt=15-bx then qt=bx.  (unchanged from R13)
// ---------------------------------------------------------------------------
#define SAT 72
#define TSZ (64 * SAT)
#define ATTN_SMEM (4 * 2 * TSZ * 2)   // 73728

__global__ __launch_bounds__(256) void attn_mma()
{
    extern __shared__ __half smh[];

    const int tid = threadIdx.x;
    const int lane = tid & 31, warp = tid >> 5;
    const int g = lane >> 2, tg = lane & 3;
    const int bx = blockIdx.x;        // 0..7
    const int bh = blockIdx.y;

    const __half* Qb = g_Q16 + (size_t)bh * TT * HD;
    const __half* Kg = g_K16 + (size_t)bh * TT * HD;
    const __half* Vg = g_V16 + (size_t)bh * HD * TT;

    const int cr = tid >> 2, cc = (tid & 3) * 16;
    const int nrow = (lane & 7) + (lane >> 4) * 8;
    const int ksel = (lane >> 3) & 1;

    auto issue = [&](int j, int st) {
        uint32_t sb = (uint32_t)__cvta_generic_to_shared(
            smh + st * 2 * TSZ + cr * SAT + cc);
        const __half* kp = Kg + (size_t)(j * 64 + cr) * HD + cc;
        const __half* vp = Vg + (size_t)cr * TT + j * 64 + cc;
        cp16(sb,           kp); cp16(sb + 16,           kp + 8);
        cp16(sb + TSZ * 2, vp); cp16(sb + TSZ * 2 + 16, vp + 8);
    };

    const uint32_t smb = (uint32_t)__cvta_generic_to_shared(smh);

#pragma unroll 1
    for (int half = 0; half < 2; half++) {
        const int qt = half ? bx : (15 - bx);

        const __half* Qg = Qb + (size_t)qt * 128 * HD;
        uint32_t qf[4][4];
        {
            const int r0 = warp * 16 + g;
#pragma unroll
            for (int s = 0; s < 4; s++) {
                int base = r0 * HD + s * 16 + 2 * tg;
                qf[s][0] = *(const uint32_t*)&Qg[base];
                qf[s][1] = *(const uint32_t*)&Qg[base + 8 * HD];
                qf[s][2] = *(const uint32_t*)&Qg[base + 8];
                qf[s][3] = *(const uint32_t*)&Qg[base + 8 * HD + 8];
            }
        }

        float accO[8][4];
#pragma unroll
        for (int jo = 0; jo < 8; jo++)
#pragma unroll
            for (int r = 0; r < 4; r++) accO[jo][r] = 0.f;
        float l0 = 0.f, l1 = 0.f;

        const int jmax = 2 * qt + 1;
        const int rowg = qt * 128 + warp * 16 + g;
        const int rmax = qt * 128 + warp * 16 + 15;

        issue(0, 0); cpcommit();
        issue(1, 1); cpcommit();

        for (int j = 0; j <= jmax; j++) {
            const int st = j & 3;
            if (j + 2 <= jmax) { issue(j + 2, (j + 2) & 3); cpcommit(); }
            if (j + 2 <= jmax)      cpwait<2>();
            else if (j + 1 <= jmax) cpwait<1>();
            else                    cpwait<0>();
            __syncthreads();

            if (j * 64 <= rmax) {
                const uint32_t skb = smb + (st * 2 * TSZ) * 2;
                const uint32_t svb = skb + TSZ * 2;

                float S[8][4];
#pragma unroll
                for (int jn = 0; jn < 8; jn++)
#pragma unroll
                    for (int r = 0; r < 4; r++) S[jn][r] = 0.f;

#pragma unroll
                for (int s = 0; s < 4; s++) {
#pragma unroll
                    for (int jp = 0; jp < 4; jp++) {
                        uint32_t th[4];
                        ldsm4(th, skb + ((jp * 16 + nrow) * SAT + s * 16 + ksel * 8) * 2);
                        mma_f16(S[2*jp],     qf[s], th);
                        mma_f16(S[2*jp + 1], qf[s], th + 2);
                    }
                }

                const bool diag = (j >= 2 * qt);
#pragma unroll
                for (int jn = 0; jn < 8; jn++) {
                    int kb = j * 64 + jn * 8 + 2 * tg;
                    float p0, p1, p2, p3;
                    if (diag) {
                        p0 = (kb     <= rowg    ) ? ex2(S[jn][0]) : 0.f;
                        p1 = (kb + 1 <= rowg    ) ? ex2(S[jn][1]) : 0.f;
                        p2 = (kb     <= rowg + 8) ? ex2(S[jn][2]) : 0.f;
                        p3 = (kb + 1 <= rowg + 8) ? ex2(S[jn][3]) : 0.f;
                    } else {
                        p0 = ex2(S[jn][0]); p1 = ex2(S[jn][1]);
                        p2 = ex2(S[jn][2]); p3 = ex2(S[jn][3]);
                    }
                    S[jn][0] = p0; S[jn][1] = p1; S[jn][2] = p2; S[jn][3] = p3;
                    l0 += p0 + p1; l1 += p2 + p3;
                }

                uint32_t pf[4][4];
#pragma unroll
                for (int t = 0; t < 4; t++) {
                    pf[t][0] = pkh(S[2*t][0],   S[2*t][1]);
                    pf[t][1] = pkh(S[2*t][2],   S[2*t][3]);
                    pf[t][2] = pkh(S[2*t+1][0], S[2*t+1][1]);
                    pf[t][3] = pkh(S[2*t+1][2], S[2*t+1][3]);
                }

#pragma unroll
                for (int t = 0; t < 4; t++) {
#pragma unroll
                    for (int jp = 0; jp < 4; jp++) {
                        uint32_t th[4];
                        ldsm4(th, svb + ((jp * 16 + nrow) * SAT + t * 16 + ksel * 8) * 2);
                        mma_f16(accO[2*jp],     pf[t], th);
                        mma_f16(accO[2*jp + 1], pf[t], th + 2);
                    }
                }
            }
        }

        l0 += __shfl_xor_sync(0xffffffffu, l0, 1);
        l0 += __shfl_xor_sync(0xffffffffu, l0, 2);
        l1 += __shfl_xor_sync(0xffffffffu, l1, 1);
        l1 += __shfl_xor_sync(0xffffffffu, l1, 2);
        const float inv0 = 1.0f / l0, inv1 = 1.0f / l1;

        const int b = bh / HH, h = bh % HH;
        const int t0 = qt * 128 + warp * 16 + g;
#pragma unroll
        for (int jo = 0; jo < 8; jo++) {
            int d = h * HD + jo * 8 + 2 * tg;
            const size_t e0 = ((size_t)b * TT + t0) * DD + d;
            const size_t e1 = ((size_t)b * TT + t0 + 8) * DD + d;
            *(uint32_t*)&g_X16[e0] = pkh(accO[jo][0] * inv0, accO[jo][1] * inv0);
            *(uint32_t*)&g_X16[e1] = pkh(accO[jo][2] * inv1, accO[jo][3] * inv1);
        }
        __syncthreads();   // smem ring quiesced before next half re-issues
    }
}

// ---------------------------------------------------------------------------
extern "C" void kernel_launch(void* const* d_in, const int* in_sizes, int n_in,
                              void* d_out, int out_size)
{
    const float* x    = (const float*)d_in[0];
    const float* wq   = (const float*)d_in[1];
    const float* wk   = (const float*)d_in[2];
    const float* wv   = (const float*)d_in[3];
    const float* wo   = (const float*)d_in[4];
    const float* cosT = (const float*)d_in[5];
    const float* sinT = (const float*)d_in[6];
    float* out = (float*)d_out;

    __half *x16, *w16, *q16, *k16, *v16;
    cudaGetSymbolAddress((void**)&x16, g_X16);
    cudaGetSymbolAddress((void**)&w16, g_W16);
    cudaGetSymbolAddress((void**)&q16, g_Q16);
    cudaGetSymbolAddress((void**)&k16, g_K16);
    cudaGetSymbolAddress((void**)&v16, g_V16);

    cudaFuncSetAttribute(gemm_h,
                         cudaFuncAttributeMaxDynamicSharedMemorySize, GEMM_SMEM);
    cudaFuncSetAttribute(attn_mma,
                         cudaFuncAttributeMaxDynamicSharedMemorySize, ATTN_SMEM);

    conv_all<<<2048, 256>>>(x, wq, wk, wv, wo, x16, w16);

    // Fused QKV: N = 3072, grid (12, 32), 512 threads
    gemm_h<<<dim3(12, MM / 128), 512, GEMM_SMEM>>>(
        x16, w16, q16, k16, v16, nullptr, cosT, sinT, 1);
    // Paired causal tiles: grid (8, 32)
    attn_mma<<<dim3(8, BB * HH), 256, ATTN_SMEM>>>();
    // Output projection: N = 1024, grid (4, 32), 512 threads
    gemm_h<<<dim3(4, MM / 128), 512, GEMM_SMEM>>>(
        x16, w16 + 3 * WSZ, nullptr, nullptr, nullptr, out, cosT, sinT, 0);
}